// round 13
// baseline (speedup 1.0000x reference)
#include <cuda_runtime.h>
#include <math.h>
#include <float.h>

#define NN 50000
#define NE 800000
#define FF 10
#define TT 5
#define TF 50
#define QP 64          // padded row stride for d_p / d_q (256B-aligned rows)
#define GG 64

// ---------------- device scratch (postcondition-restored each run) ----------
static __device__ int      d_deg[NN];          // zero at entry, re-zeroed by k_bnpool
static __device__ int      d_offs[NN];
static __device__ int      d_cursor[NN];       // fully overwritten by k_prep each run
static __device__ int      d_ecnt;             // slot counter, re-zeroed by k_final
static __device__ float    d_logsum;           // re-zeroed by k_final
static __device__ unsigned d_csr[NE];          // (src*256 byte-offset) bits 0..23 | attr<<28
static __device__ float    d_h[NN * FF];
static __device__ __align__(256) float d_p[NN * QP];   // pads never written -> stay 0
static __device__ __align__(256) float d_q[NN * QP];
static __device__ float    d_o[NN * FF];
static __device__ float    d_bn2[2 * 2 * FF];  // [layer][sum|sumsq][FF]; re-zeroed by k_final
static __device__ float    d_pool[GG * FF];    // re-zeroed by k_final

// ---------------- f32x2 packed helpers (sm_103a) -----------------------------
typedef unsigned long long ull;
__device__ __forceinline__ ull pk2f(float x, float y) {
    ull u; asm("mov.b64 %0,{%1,%2};" : "=l"(u) : "f"(x), "f"(y)); return u;
}
__device__ __forceinline__ void upk2f(ull u, float& x, float& y) {
    asm("mov.b64 {%0,%1},%2;" : "=f"(x), "=f"(y) : "l"(u));
}
__device__ __forceinline__ ull add2f(ull a, ull b) {
    ull r; asm("add.rn.f32x2 %0,%1,%2;" : "=l"(r) : "l"(a), "l"(b)); return r;
}
__device__ __forceinline__ ull fma2f(ull a, ull b, ull c) {
    ull r; asm("fma.rn.f32x2 %0,%1,%2,%3;" : "=l"(r) : "l"(a), "l"(b), "l"(c)); return r;
}
__device__ __forceinline__ ull shfl_xor64(ull v, int m) {
    unsigned lo = (unsigned)v, hi = (unsigned)(v >> 32);
    lo = __shfl_xor_sync(0xffffffffu, lo, m);
    hi = __shfl_xor_sync(0xffffffffu, hi, m);
    return ((ull)hi << 32) | lo;
}

// ---------------- fused h-producer + p/q projection (+ degree count) --------
__global__ void __launch_bounds__(256) k_pq(
    const float* __restrict__ x,
    const float* __restrict__ m1w1, const float* __restrict__ m1b1,
    const float* __restrict__ m1w2, const float* __restrict__ m1b2,
    const float* __restrict__ gamma, const float* __restrict__ beta,
    const float* __restrict__ prew,
    const int* __restrict__ ei, int l, int mode)
{
    __shared__ float sh_x[4][FF];
    __shared__ float sh_hid[4][5];
    __shared__ float sh_h[4][FF];
    const int tid = threadIdx.x;
    if (mode == 0) {
        int gid = blockIdx.x * 256 + tid;              // 12500*256 = 3.2M >= NE
        if (gid < NE) {
            int dst = ei[NE + gid];
            if (dst >= 0 && dst < NN) atomicAdd(&d_deg[dst], 1);
        }
    }
    const int g = tid >> 6;
    const int tf = tid & 63;
    const int n = blockIdx.x * 4 + g;
    const bool valid = (n < NN);
    if (mode == 0) {
        if (valid && tf < FF) sh_x[g][tf] = x[n * FF + tf];
        __syncthreads();
        if (valid && tf < 5) {
            float hj = __ldg(&m1b1[tf]);
#pragma unroll
            for (int k = 0; k < FF; k++)
                hj = fmaf(sh_x[g][k], __ldg(&m1w1[k * 5 + tf]), hj);
            sh_hid[g][tf] = fmaxf(hj, 0.f);
        }
        __syncthreads();
        if (valid && tf < FF) {
            float v = __ldg(&m1b2[tf]);
#pragma unroll
            for (int j = 0; j < 5; j++)
                v = fmaf(sh_hid[g][j], __ldg(&m1w2[j * FF + tf]), v);
            sh_h[g][tf] = v;
            d_h[n * FF + tf] = v;
        }
    } else {
        if (valid && tf < FF) {
            float mu  = d_bn2[tf] / (float)NN;
            float var = d_bn2[FF + tf] / (float)NN - mu * mu;
            float v = (d_o[n * FF + tf] - mu) * rsqrtf(var + 1e-5f)
                * __ldg(&gamma[(l - 1) * FF + tf]) + __ldg(&beta[(l - 1) * FF + tf]);
            v = fmaxf(v, 0.f);
            sh_h[g][tf] = v;
            d_h[n * FF + tf] = v;
        }
    }
    __syncthreads();
    if (!valid || tf >= TF) return;
    const int t = tf / FF, f = tf % FF;
    const float* W = prew + (size_t)(l * TT + t) * 3 * FF * FF;
    float ap = 0.f, aq = 0.f;
#pragma unroll
    for (int k = 0; k < FF; k++) {
        float hk = sh_h[g][k];
        ap = fmaf(hk, __ldg(&W[k * FF + f]), ap);
        aq = fmaf(hk, __ldg(&W[(FF + k) * FF + f]), aq);
    }
    d_p[n * QP + tf] = ap;
    d_q[n * QP + tf] = aq;
}

// parallel slot-grab CSR offsets (order-free) + log-degree sum; seeds cursor
__global__ void k_prep() {
    int n = blockIdx.x * blockDim.x + threadIdx.x;
    int lane = threadIdx.x & 31;
    int dg = (n < NN) ? d_deg[n] : 0;
    int inc = dg;
#pragma unroll
    for (int o = 1; o < 32; o <<= 1) {
        int u = __shfl_up_sync(0xffffffffu, inc, o);
        if (lane >= o) inc += u;
    }
    int total = __shfl_sync(0xffffffffu, inc, 31);
    int base = 0;
    if (lane == 31 && total > 0) base = atomicAdd(&d_ecnt, total);
    base = __shfl_sync(0xffffffffu, base, 31);
    if (n < NN) {
        int off = base + inc - dg;
        d_offs[n] = off;
        d_cursor[n] = off;       // fill grabs slots directly from here
    }
    float ls = (n < NN) ? logf((float)dg + 1.f) : 0.f;
#pragma unroll
    for (int o = 16; o; o >>= 1) ls += __shfl_xor_sync(0xffffffffu, ls, o);
    if (lane == 0) atomicAdd(&d_logsum, ls);
}

// 2 edges per thread via int2 loads
__global__ void k_fill(const int* __restrict__ ei, const int* __restrict__ eattr) {
    int i2 = blockIdx.x * blockDim.x + threadIdx.x;   // edge pair index
    if (i2 * 2 >= NE) return;
    int2 srcs = *(const int2*)(ei + 2 * i2);
    int2 dsts = *(const int2*)(ei + NE + 2 * i2);
    int2 atts = *(const int2*)(eattr + 2 * i2);
    {
        int src = srcs.x, dst = dsts.x, attr = atts.x & 3;
        if (dst >= 0 && dst < NN) {
            if (src < 0 || src >= NN) src = 0;
            int slot = atomicAdd(&d_cursor[dst], 1);
            if (slot >= 0 && slot < NE)
                d_csr[slot] = ((unsigned)src << 8) | ((unsigned)attr << 28);
        }
    }
    {
        int src = srcs.y, dst = dsts.y, attr = atts.y & 3;
        if (dst >= 0 && dst < NN) {
            if (src < 0 || src >= NN) src = 0;
            int slot = atomicAdd(&d_cursor[dst], 1);
            if (slot >= 0 && slot < NE)
                d_csr[slot] = ((unsigned)src << 8) | ((unsigned)attr << 28);
        }
    }
}

// warp-per-node: float2 gather + packed-f32x2 stats of m=p+q+c3,
// jj-packed post matvec + lin + BN sums. Occupancy forced to 8 blocks/SM.
__global__ void __launch_bounds__(256, 8) k_agg(
    const float* __restrict__ eemb,  const float* __restrict__ encw,
    const float* __restrict__ encb,  const float* __restrict__ prew,
    const float* __restrict__ preb,
    const float* __restrict__ postw, const float* __restrict__ postb,
    const float* __restrict__ linw,  const float* __restrict__ linb, int l)
{
    __shared__ float e4[4 * FF];
    __shared__ __align__(8) float sh_c3[4 * 64];     // padded to 64, pads = 0
    __shared__ __align__(8) float sh_pw2[TT * 288];  // [t][row*2+jj], rows>129 zero pad
    __shared__ float sh_pb[10];
    __shared__ float sh_lw[FF * FF];
    __shared__ float sh_lb[FF];
    __shared__ float sh_xt[8][FF];
    __shared__ __align__(8) float sh_st[8][4][TF];   // [warp][stat][tf]
    __shared__ float sh_o10[8][10];
    __shared__ float sh_bna[2 * FF];
    __shared__ float sh_avg;
    const int tid = threadIdx.x;
    if (tid < 4 * FF) {
        int a = tid / FF, k = tid % FF;
        float v = __ldg(&encb[l * FF + k]);
#pragma unroll
        for (int j = 0; j < FF; j++)
            v = fmaf(__ldg(&eemb[a * FF + j]), __ldg(&encw[(l * FF + j) * FF + k]), v);
        e4[tid] = v;
    }
    for (int idx = tid; idx < TT * 288; idx += 256) {
        int t = idx / 288, rr = idx % 288;
        sh_pw2[idx] = (rr < 260) ? postw[(l * TT + t) * 260 + rr] : 0.f;
    }
    if (tid < 10) sh_pb[tid] = postb[l * 10 + tid];
    if (tid < FF * FF) sh_lw[tid] = linw[l * FF * FF + tid];
    if (tid < FF) sh_lb[tid] = linb[l * FF + tid];
    if (tid < 2 * FF) sh_bna[tid] = 0.f;
    if (tid == 0) sh_avg = d_logsum * (1.f / (float)NN);
    __syncthreads();
    {
        int a = tid >> 6, f = tid & 63;
        float v = 0.f;
        if (f < TF) {
            int t = f / FF, ff = f % FF;
            v = __ldg(&preb[(l * TT + t) * FF + ff]);
#pragma unroll
            for (int k = 0; k < FF; k++)
                v = fmaf(e4[a * FF + k],
                         __ldg(&prew[((l * TT + t) * 3 * FF + 2 * FF + k) * FF + ff]), v);
        }
        sh_c3[a * 64 + f] = v;
    }
    __syncthreads();

    const int w = tid >> 5, lane = tid & 31;
    const int n = blockIdx.x * 8 + w;
    if (n < NN) {
        const int stt = d_offs[n];
        const int dg  = d_deg[n];
        const int enn = stt + dg;
        const float dclamp = fmaxf((float)dg, 1.f);
        const float invd = 1.f / dclamp;
        const float ld = logf(dclamp + 1.f);
        const float avg = sh_avg;
        const float amp = ld / avg, att = avg / ld;
        if (lane < FF) sh_xt[w][lane] = d_h[n * FF + lane];
        const int fl = 2 * lane;                       // 0..62 (>=50 -> padding)
        const float2 pv = *(const float2*)(d_p + n * QP + fl);
        const ull p01 = pk2f(pv.x, pv.y);
        const char* qb  = (const char*)d_q + (size_t)fl * 4;   // lane base, byte addressed
        const char* c3b = (const char*)sh_c3 + (size_t)fl * 4;
        ull s01 = 0ull, ss01 = 0ull;                   // stats of m = p + q + c3
        float mn0 = FLT_MAX, mx0 = -FLT_MAX, mn1 = FLT_MAX, mx1 = -FLT_MAX;
#define EDGE(pkv) {                                                              \
        const float2 qv = *(const float2*)(qb + ((pkv) & 0x0FFFFFFFu));          \
        const float2 cv = *(const float2*)(c3b + (((pkv) >> 28) << 8));          \
        ull m01 = add2f(add2f(p01, pk2f(qv.x, qv.y)), pk2f(cv.x, cv.y));         \
        s01 = add2f(s01, m01); ss01 = fma2f(m01, m01, ss01);                     \
        float m0, m1; upk2f(m01, m0, m1);                                        \
        mn0 = fminf(mn0, m0); mx0 = fmaxf(mx0, m0);                              \
        mn1 = fminf(mn1, m1); mx1 = fmaxf(mx1, m1); }
        int i = stt;
        for (; i + 4 <= enn; i += 4) {
            unsigned pk0 = d_csr[i],     pk1 = d_csr[i + 1];
            unsigned pk2 = d_csr[i + 2], pk3 = d_csr[i + 3];
            EDGE(pk0); EDGE(pk1); EDGE(pk2); EDGE(pk3);
        }
        for (; i < enn; i++) { unsigned pk = d_csr[i]; EDGE(pk); }
#undef EDGE
        if (fl < TF) {
            float s0, s1, ss0, ss1;
            upk2f(s01, s0, s1); upk2f(ss01, ss0, ss1);
            float mean0 = s0 * invd, mean1 = s1 * invd;
            float std0 = sqrtf(fmaxf(ss0 * invd - mean0 * mean0, 0.f) + 1e-5f);
            float std1 = sqrtf(fmaxf(ss1 * invd - mean1 * mean1, 0.f) + 1e-5f);
            bool hin = dg > 0;
            *(ull*)&sh_st[w][0][fl] = pk2f(mean0, mean1);
            *(ull*)&sh_st[w][1][fl] = pk2f(hin ? mn0 : 0.f, hin ? mn1 : 0.f);
            *(ull*)&sh_st[w][2][fl] = pk2f(hin ? mx0 : 0.f, hin ? mx1 : 0.f);
            *(ull*)&sh_st[w][3][fl] = pk2f(std0, std1);
        }
        __syncwarp();
        // jj-packed post matvec: rows r0=lane (0..31), r1=lane+32 (32..49)
        const int r0 = lane, r1 = lane + 32;
        const bool x0v = (r0 < FF);
        const int s0i = (r0 - FF) / FF, f0i = (r0 - FF) % FF;
        const int s1i = (r1 - FF) / FF, f1i = (r1 - FF) % FF;
        const bool v1 = (r1 < TF);
        const ull amppk = pk2f(amp, amp), attpk = pk2f(att, att);
#pragma unroll
        for (int t = 0; t < TT; t++) {
            const float* P = &sh_pw2[t * 288];
            float iv0 = x0v ? sh_xt[w][r0] : sh_st[w][s0i][t * FF + f0i];
            float iv1 = v1 ? sh_st[w][s1i][t * FF + f1i] : 0.f;
            ull w0 = *(const ull*)(P + 2 * r0);
            if (!x0v) {
                ull w0a = *(const ull*)(P + 2 * (r0 + 40));
                ull w0b = *(const ull*)(P + 2 * (r0 + 80));
                w0 = fma2f(amppk, w0a, fma2f(attpk, w0b, w0));
            }
            ull w1  = *(const ull*)(P + 2 * r1);
            ull w1a = *(const ull*)(P + 2 * (r1 + 40));
            ull w1b = *(const ull*)(P + 2 * (r1 + 80));   // max 2*143 < 288 (pad=0)
            w1 = fma2f(amppk, w1a, fma2f(attpk, w1b, w1));
            ull acc = fma2f(pk2f(iv0, iv0), w0, fma2f(pk2f(iv1, iv1), w1, 0ull));
            acc = add2f(acc, shfl_xor64(acc, 16));
            acc = add2f(acc, shfl_xor64(acc, 8));
            acc = add2f(acc, shfl_xor64(acc, 4));
            acc = add2f(acc, shfl_xor64(acc, 2));
            acc = add2f(acc, shfl_xor64(acc, 1));
            if (lane == 0) {
                float a0, a1; upk2f(acc, a0, a1);
                sh_o10[w][t * 2]     = a0 + sh_pb[t * 2];
                sh_o10[w][t * 2 + 1] = a1 + sh_pb[t * 2 + 1];
            }
        }
        __syncwarp();
        if (lane < FF) {
            float v = sh_lb[lane];
#pragma unroll
            for (int i2 = 0; i2 < FF; i2++)
                v = fmaf(sh_o10[w][i2], sh_lw[i2 * FF + lane], v);
            d_o[n * FF + lane] = v;
            atomicAdd(&sh_bna[lane], v);
            atomicAdd(&sh_bna[FF + lane], v * v);
        }
    }
    __syncthreads();
    if (tid < 2 * FF) atomicAdd(&d_bn2[l * 2 * FF + tid], sh_bna[tid]);
}

// final-layer BN + relu + two-stage global_add_pool; restores d_deg to zero
__global__ void __launch_bounds__(256) k_bnpool(
    const float* __restrict__ gamma, const float* __restrict__ beta,
    const int* __restrict__ batch, int l) {
    __shared__ float sh_pool[GG * FF];
    __shared__ float sh_a[FF], sh_b[FF];
    const int tid = threadIdx.x;
    for (int i = tid; i < GG * FF; i += 256) sh_pool[i] = 0.f;
    if (tid < FF) {
        float mu  = d_bn2[l * 2 * FF + tid] / (float)NN;
        float var = d_bn2[l * 2 * FF + FF + tid] / (float)NN - mu * mu;
        float a = rsqrtf(var + 1e-5f) * __ldg(&gamma[l * FF + tid]);
        sh_a[tid] = a;
        sh_b[tid] = __ldg(&beta[l * FF + tid]) - mu * a;
    }
    __syncthreads();
    int n = blockIdx.x * 256 + tid;
    if (n < NN) {
        int b = batch[n];
        if (b < 0) b = 0;
        if (b >= GG) b = GG - 1;
#pragma unroll
        for (int f = 0; f < FF; f++) {
            float v = fmaxf(fmaf(d_o[n * FF + f], sh_a[f], sh_b[f]), 0.f);
            atomicAdd(&sh_pool[b * FF + f], v);
        }
        d_deg[n] = 0;          // postcondition restore for next run
    }
    __syncthreads();
    for (int i = tid; i < GG * FF; i += 256) {
        float v = sh_pool[i];
        if (v != 0.f) atomicAdd(&d_pool[i], v);
    }
}

// readout; restores d_pool, d_bn2, d_ecnt, d_logsum
__global__ void k_final(const float* __restrict__ w1, const float* __restrict__ b1,
                        const float* __restrict__ w2, const float* __restrict__ b2,
                        float* __restrict__ out) {
    int g = threadIdx.x;
    if (g < 2 * 2 * FF) d_bn2[g] = 0.f;
    if (g == 0) { d_ecnt = 0; d_logsum = 0.f; }
    if (g >= GG) return;
    float pv[FF];
#pragma unroll
    for (int k = 0; k < FF; k++) { pv[k] = d_pool[g * FF + k]; d_pool[g * FF + k] = 0.f; }
    float o = b2[0];
#pragma unroll
    for (int j = 0; j < 5; j++) {
        float hj = b1[j];
#pragma unroll
        for (int k = 0; k < FF; k++) hj += pv[k] * w1[k * 5 + j];
        o += fmaxf(hj, 0.f) * w2[j];
    }
    out[g] = o;
}

// ---------------- launch -----------------------------------------------------
extern "C" void kernel_launch(void* const* d_in, const int* in_sizes, int n_in,
                              void* d_out, int out_size) {
    const float* x        = (const float*)d_in[0];
    const float* edge_emb = (const float*)d_in[1];
    const float* mlp1_w1  = (const float*)d_in[2];
    const float* mlp1_b1  = (const float*)d_in[3];
    const float* mlp1_w2  = (const float*)d_in[4];
    const float* mlp1_b2  = (const float*)d_in[5];
    const float* enc_w    = (const float*)d_in[6];
    const float* enc_b    = (const float*)d_in[7];
    const float* pre_w    = (const float*)d_in[8];
    const float* pre_b    = (const float*)d_in[9];
    const float* post_w   = (const float*)d_in[10];
    const float* post_b   = (const float*)d_in[11];
    const float* lin_w    = (const float*)d_in[12];
    const float* lin_b    = (const float*)d_in[13];
    const float* bn_gamma = (const float*)d_in[14];
    const float* bn_beta  = (const float*)d_in[15];
    const float* mlp2_w1  = (const float*)d_in[16];
    const float* mlp2_b1  = (const float*)d_in[17];
    const float* mlp2_w2  = (const float*)d_in[18];
    const float* mlp2_b2  = (const float*)d_in[19];
    const int* edge_index = (const int*)d_in[20];
    const int* edge_attr  = (const int*)d_in[21];
    const int* batch      = (const int*)d_in[22];
    float* out = (float*)d_out;

    const int TB = 256;
    k_pq<<<(NN + 3) / 4, 256>>>(x, mlp1_w1, mlp1_b1, mlp1_w2, mlp1_b2,
                                bn_gamma, bn_beta, pre_w, edge_index, 0, 0);
    k_prep<<<(NN + TB - 1) / TB, TB>>>();
    k_fill<<<(NE / 2 + TB - 1) / TB, TB>>>(edge_index, edge_attr);
    k_agg<<<(NN + 7) / 8, 256>>>(edge_emb, enc_w, enc_b, pre_w, pre_b,
                                 post_w, post_b, lin_w, lin_b, 0);
    k_pq<<<(NN + 3) / 4, 256>>>(x, mlp1_w1, mlp1_b1, mlp1_w2, mlp1_b2,
                                bn_gamma, bn_beta, pre_w, edge_index, 1, 1);
    k_agg<<<(NN + 7) / 8, 256>>>(edge_emb, enc_w, enc_b, pre_w, pre_b,
                                 post_w, post_b, lin_w, lin_b, 1);
    k_bnpool<<<(NN + TB - 1) / TB, TB>>>(bn_gamma, bn_beta, batch, 1);
    k_final<<<1, 64>>>(mlp2_w1, mlp2_b1, mlp2_w2, mlp2_b2, out);
}

// round 14
// speedup vs baseline: 1.0045x; 1.0045x over previous
#include <cuda_runtime.h>
#include <math.h>
#include <float.h>

#define NN 50000
#define NE 800000
#define FF 10
#define TT 5
#define TF 50
#define QP 64          // padded row stride for d_p / d_q (256B-aligned rows)
#define GG 64

// ---------------- device scratch (postcondition-restored each run) ----------
static __device__ int      d_deg[NN];          // zero at entry, re-zeroed by k_bnpool
static __device__ int      d_offs[NN];
static __device__ int      d_cursor[NN];       // fully overwritten by k_prep each run
static __device__ int      d_ecnt;             // slot counter, re-zeroed by k_final
static __device__ float    d_logsum;           // re-zeroed by k_final
static __device__ unsigned d_csr[NE];          // (src*256 byte-offset) bits 0..23 | attr<<28
static __device__ float    d_h[NN * FF];
static __device__ __align__(256) float d_p[NN * QP];   // pads never written -> stay 0
static __device__ __align__(256) float d_q[NN * QP];
static __device__ float    d_o[NN * FF];
static __device__ float    d_bn2[2 * 2 * FF];  // [layer][sum|sumsq][FF]; re-zeroed by k_final
static __device__ float    d_pool[GG * FF];    // re-zeroed by k_final
static __device__ float    d_c3g[2 * 256];     // prepacked c3 tables (padded to 64/attr)
static __device__ float    d_pw2g[2 * TT * 288]; // prepacked jj-paired post_w

// ---------------- f32x2 packed helpers (sm_103a) -----------------------------
typedef unsigned long long ull;
__device__ __forceinline__ ull pk2f(float x, float y) {
    ull u; asm("mov.b64 %0,{%1,%2};" : "=l"(u) : "f"(x), "f"(y)); return u;
}
__device__ __forceinline__ void upk2f(ull u, float& x, float& y) {
    asm("mov.b64 {%0,%1},%2;" : "=f"(x), "=f"(y) : "l"(u));
}
__device__ __forceinline__ ull add2f(ull a, ull b) {
    ull r; asm("add.rn.f32x2 %0,%1,%2;" : "=l"(r) : "l"(a), "l"(b)); return r;
}
__device__ __forceinline__ ull fma2f(ull a, ull b, ull c) {
    ull r; asm("fma.rn.f32x2 %0,%1,%2,%3;" : "=l"(r) : "l"(a), "l"(b), "l"(c)); return r;
}
__device__ __forceinline__ ull shfl_xor64(ull v, int m) {
    unsigned lo = (unsigned)v, hi = (unsigned)(v >> 32);
    lo = __shfl_xor_sync(0xffffffffu, lo, m);
    hi = __shfl_xor_sync(0xffffffffu, hi, m);
    return ((ull)hi << 32) | lo;
}

// ---------------- per-layer table prepack (grid = 2, one block per layer) ----
__global__ void k_etab(const float* __restrict__ eemb,
                       const float* __restrict__ encw, const float* __restrict__ encb,
                       const float* __restrict__ prew, const float* __restrict__ preb,
                       const float* __restrict__ postw) {
    const int l = blockIdx.x;
    const int tid = threadIdx.x;
    __shared__ float e4[4 * FF];
    if (tid < 4 * FF) {
        int a = tid / FF, k = tid % FF;
        float v = __ldg(&encb[l * FF + k]);
#pragma unroll
        for (int j = 0; j < FF; j++)
            v = fmaf(__ldg(&eemb[a * FF + j]), __ldg(&encw[(l * FF + j) * FF + k]), v);
        e4[tid] = v;
    }
    __syncthreads();
    {   // c3[a][f] padded to 64 per attr
        int a = tid >> 6, f = tid & 63;
        float v = 0.f;
        if (f < TF) {
            int t = f / FF, ff = f % FF;
            v = __ldg(&preb[(l * TT + t) * FF + ff]);
#pragma unroll
            for (int k = 0; k < FF; k++)
                v = fmaf(e4[a * FF + k],
                         __ldg(&prew[((l * TT + t) * 3 * FF + 2 * FF + k) * FF + ff]), v);
        }
        d_c3g[l * 256 + tid] = v;
    }
    for (int idx = tid; idx < TT * 288; idx += 256) {
        int t = idx / 288, rr = idx % 288;
        d_pw2g[l * TT * 288 + idx] = (rr < 260) ? postw[(l * TT + t) * 260 + rr] : 0.f;
    }
}

// ---------------- fused h-producer + p/q projection (+ degree count) --------
__global__ void __launch_bounds__(256) k_pq(
    const float* __restrict__ x,
    const float* __restrict__ m1w1, const float* __restrict__ m1b1,
    const float* __restrict__ m1w2, const float* __restrict__ m1b2,
    const float* __restrict__ gamma, const float* __restrict__ beta,
    const float* __restrict__ prew,
    const int* __restrict__ ei, int l, int mode)
{
    __shared__ float sh_x[4][FF];
    __shared__ float sh_hid[4][5];
    __shared__ float sh_h[4][FF];
    const int tid = threadIdx.x;
    if (mode == 0) {
        int gid = blockIdx.x * 256 + tid;              // 12500*256 = 3.2M >= NE
        if (gid < NE) {
            int dst = ei[NE + gid];
            if (dst >= 0 && dst < NN) atomicAdd(&d_deg[dst], 1);
        }
    }
    const int g = tid >> 6;
    const int tf = tid & 63;
    const int n = blockIdx.x * 4 + g;
    const bool valid = (n < NN);
    if (mode == 0) {
        if (valid && tf < FF) sh_x[g][tf] = x[n * FF + tf];
        __syncthreads();
        if (valid && tf < 5) {
            float hj = __ldg(&m1b1[tf]);
#pragma unroll
            for (int k = 0; k < FF; k++)
                hj = fmaf(sh_x[g][k], __ldg(&m1w1[k * 5 + tf]), hj);
            sh_hid[g][tf] = fmaxf(hj, 0.f);
        }
        __syncthreads();
        if (valid && tf < FF) {
            float v = __ldg(&m1b2[tf]);
#pragma unroll
            for (int j = 0; j < 5; j++)
                v = fmaf(sh_hid[g][j], __ldg(&m1w2[j * FF + tf]), v);
            sh_h[g][tf] = v;
            d_h[n * FF + tf] = v;
        }
    } else {
        if (valid && tf < FF) {
            float mu  = d_bn2[tf] / (float)NN;
            float var = d_bn2[FF + tf] / (float)NN - mu * mu;
            float v = (d_o[n * FF + tf] - mu) * rsqrtf(var + 1e-5f)
                * __ldg(&gamma[(l - 1) * FF + tf]) + __ldg(&beta[(l - 1) * FF + tf]);
            v = fmaxf(v, 0.f);
            sh_h[g][tf] = v;
            d_h[n * FF + tf] = v;
        }
    }
    __syncthreads();
    if (!valid || tf >= TF) return;
    const int t = tf / FF, f = tf % FF;
    const float* W = prew + (size_t)(l * TT + t) * 3 * FF * FF;
    float ap = 0.f, aq = 0.f;
#pragma unroll
    for (int k = 0; k < FF; k++) {
        float hk = sh_h[g][k];
        ap = fmaf(hk, __ldg(&W[k * FF + f]), ap);
        aq = fmaf(hk, __ldg(&W[(FF + k) * FF + f]), aq);
    }
    d_p[n * QP + tf] = ap;
    d_q[n * QP + tf] = aq;
}

// parallel slot-grab CSR offsets (order-free) + log-degree sum; seeds cursor
__global__ void k_prep() {
    int n = blockIdx.x * blockDim.x + threadIdx.x;
    int lane = threadIdx.x & 31;
    int dg = (n < NN) ? d_deg[n] : 0;
    int inc = dg;
#pragma unroll
    for (int o = 1; o < 32; o <<= 1) {
        int u = __shfl_up_sync(0xffffffffu, inc, o);
        if (lane >= o) inc += u;
    }
    int total = __shfl_sync(0xffffffffu, inc, 31);
    int base = 0;
    if (lane == 31 && total > 0) base = atomicAdd(&d_ecnt, total);
    base = __shfl_sync(0xffffffffu, base, 31);
    if (n < NN) {
        int off = base + inc - dg;
        d_offs[n] = off;
        d_cursor[n] = off;       // fill grabs slots directly from here
    }
    float ls = (n < NN) ? logf((float)dg + 1.f) : 0.f;
#pragma unroll
    for (int o = 16; o; o >>= 1) ls += __shfl_xor_sync(0xffffffffu, ls, o);
    if (lane == 0) atomicAdd(&d_logsum, ls);
}

// 2 edges per thread via int2 loads
__global__ void k_fill(const int* __restrict__ ei, const int* __restrict__ eattr) {
    int i2 = blockIdx.x * blockDim.x + threadIdx.x;   // edge pair index
    if (i2 * 2 >= NE) return;
    int2 srcs = *(const int2*)(ei + 2 * i2);
    int2 dsts = *(const int2*)(ei + NE + 2 * i2);
    int2 atts = *(const int2*)(eattr + 2 * i2);
    {
        int src = srcs.x, dst = dsts.x, attr = atts.x & 3;
        if (dst >= 0 && dst < NN) {
            if (src < 0 || src >= NN) src = 0;
            int slot = atomicAdd(&d_cursor[dst], 1);
            if (slot >= 0 && slot < NE)
                d_csr[slot] = ((unsigned)src << 8) | ((unsigned)attr << 28);
        }
    }
    {
        int src = srcs.y, dst = dsts.y, attr = atts.y & 3;
        if (dst >= 0 && dst < NN) {
            if (src < 0 || src >= NN) src = 0;
            int slot = atomicAdd(&d_cursor[dst], 1);
            if (slot >= 0 && slot < NE)
                d_csr[slot] = ((unsigned)src << 8) | ((unsigned)attr << 28);
        }
    }
}

// warp-per-node (16 nodes / 512-thread block): float2 gather + packed-f32x2
// stats of m=p+q+c3, jj-packed post matvec + lin + BN sums. Tables preloaded.
__global__ void __launch_bounds__(512, 4) k_agg(
    const float* __restrict__ linw, const float* __restrict__ linb,
    const float* __restrict__ postb, int l)
{
    __shared__ __align__(8) float sh_c3[4 * 64];     // padded to 64, pads = 0
    __shared__ __align__(8) float sh_pw2[TT * 288];  // [t][row*2+jj], rows>129 zero pad
    __shared__ float sh_pb[10];
    __shared__ float sh_lw[FF * FF];
    __shared__ float sh_lb[FF];
    __shared__ float sh_xt[16][FF];
    __shared__ __align__(8) float sh_st[16][4][TF];  // [warp][stat][tf]
    __shared__ float sh_o10[16][10];
    __shared__ float sh_bna[2 * FF];
    __shared__ float sh_avg;
    const int tid = threadIdx.x;
    if (tid < 256) sh_c3[tid] = d_c3g[l * 256 + tid];
    for (int idx = tid; idx < TT * 288; idx += 512)
        sh_pw2[idx] = d_pw2g[l * TT * 288 + idx];
    if (tid < 10) sh_pb[tid] = postb[l * 10 + tid];
    if (tid < FF * FF) sh_lw[tid] = linw[l * FF * FF + tid];
    if (tid < FF) sh_lb[tid] = linb[l * FF + tid];
    if (tid < 2 * FF) sh_bna[tid] = 0.f;
    if (tid == 0) sh_avg = d_logsum * (1.f / (float)NN);
    __syncthreads();

    const int w = tid >> 5, lane = tid & 31;
    const int n = blockIdx.x * 16 + w;
    if (n < NN) {
        const int stt = d_offs[n];
        const int dg  = d_deg[n];
        const int enn = stt + dg;
        const float dclamp = fmaxf((float)dg, 1.f);
        const float invd = 1.f / dclamp;
        const float ld = logf(dclamp + 1.f);
        const float avg = sh_avg;
        const float amp = ld / avg, att = avg / ld;
        if (lane < FF) sh_xt[w][lane] = d_h[n * FF + lane];
        const int fl = 2 * lane;                       // 0..62 (>=50 -> padding)
        const float2 pv = *(const float2*)(d_p + n * QP + fl);
        const ull p01 = pk2f(pv.x, pv.y);
        const char* qb  = (const char*)d_q + (size_t)fl * 4;   // lane base, byte addressed
        const char* c3b = (const char*)sh_c3 + (size_t)fl * 4;
        ull s01 = 0ull, ss01 = 0ull;                   // stats of m = p + q + c3
        float mn0 = FLT_MAX, mx0 = -FLT_MAX, mn1 = FLT_MAX, mx1 = -FLT_MAX;
#define EDGE(pkv) {                                                              \
        const float2 qv = *(const float2*)(qb + ((pkv) & 0x0FFFFFFFu));          \
        const float2 cv = *(const float2*)(c3b + (((pkv) >> 28) << 8));          \
        ull m01 = add2f(add2f(p01, pk2f(qv.x, qv.y)), pk2f(cv.x, cv.y));         \
        s01 = add2f(s01, m01); ss01 = fma2f(m01, m01, ss01);                     \
        float m0, m1; upk2f(m01, m0, m1);                                        \
        mn0 = fminf(mn0, m0); mx0 = fmaxf(mx0, m0);                              \
        mn1 = fminf(mn1, m1); mx1 = fmaxf(mx1, m1); }
        int i = stt;
        for (; i + 4 <= enn; i += 4) {
            unsigned pk0 = d_csr[i],     pk1 = d_csr[i + 1];
            unsigned pk2 = d_csr[i + 2], pk3 = d_csr[i + 3];
            EDGE(pk0); EDGE(pk1); EDGE(pk2); EDGE(pk3);
        }
        for (; i < enn; i++) { unsigned pk = d_csr[i]; EDGE(pk); }
#undef EDGE
        if (fl < TF) {
            float s0, s1, ss0, ss1;
            upk2f(s01, s0, s1); upk2f(ss01, ss0, ss1);
            float mean0 = s0 * invd, mean1 = s1 * invd;
            float std0 = sqrtf(fmaxf(ss0 * invd - mean0 * mean0, 0.f) + 1e-5f);
            float std1 = sqrtf(fmaxf(ss1 * invd - mean1 * mean1, 0.f) + 1e-5f);
            bool hin = dg > 0;
            *(ull*)&sh_st[w][0][fl] = pk2f(mean0, mean1);
            *(ull*)&sh_st[w][1][fl] = pk2f(hin ? mn0 : 0.f, hin ? mn1 : 0.f);
            *(ull*)&sh_st[w][2][fl] = pk2f(hin ? mx0 : 0.f, hin ? mx1 : 0.f);
            *(ull*)&sh_st[w][3][fl] = pk2f(std0, std1);
        }
        __syncwarp();
        // jj-packed post matvec: rows r0=lane (0..31), r1=lane+32 (32..49)
        const int r0 = lane, r1 = lane + 32;
        const bool x0v = (r0 < FF);
        const int s0i = (r0 - FF) / FF, f0i = (r0 - FF) % FF;
        const int s1i = (r1 - FF) / FF, f1i = (r1 - FF) % FF;
        const bool v1 = (r1 < TF);
        const ull amppk = pk2f(amp, amp), attpk = pk2f(att, att);
#pragma unroll
        for (int t = 0; t < TT; t++) {
            const float* P = &sh_pw2[t * 288];
            float iv0 = x0v ? sh_xt[w][r0] : sh_st[w][s0i][t * FF + f0i];
            float iv1 = v1 ? sh_st[w][s1i][t * FF + f1i] : 0.f;
            ull w0 = *(const ull*)(P + 2 * r0);
            if (!x0v) {
                ull w0a = *(const ull*)(P + 2 * (r0 + 40));
                ull w0b = *(const ull*)(P + 2 * (r0 + 80));
                w0 = fma2f(amppk, w0a, fma2f(attpk, w0b, w0));
            }
            ull w1  = *(const ull*)(P + 2 * r1);
            ull w1a = *(const ull*)(P + 2 * (r1 + 40));
            ull w1b = *(const ull*)(P + 2 * (r1 + 80));   // max 2*143 < 288 (pad=0)
            w1 = fma2f(amppk, w1a, fma2f(attpk, w1b, w1));
            ull acc = fma2f(pk2f(iv0, iv0), w0, fma2f(pk2f(iv1, iv1), w1, 0ull));
            acc = add2f(acc, shfl_xor64(acc, 16));
            acc = add2f(acc, shfl_xor64(acc, 8));
            acc = add2f(acc, shfl_xor64(acc, 4));
            acc = add2f(acc, shfl_xor64(acc, 2));
            acc = add2f(acc, shfl_xor64(acc, 1));
            if (lane == 0) {
                float a0, a1; upk2f(acc, a0, a1);
                sh_o10[w][t * 2]     = a0 + sh_pb[t * 2];
                sh_o10[w][t * 2 + 1] = a1 + sh_pb[t * 2 + 1];
            }
        }
        __syncwarp();
        if (lane < FF) {
            float v = sh_lb[lane];
#pragma unroll
            for (int i2 = 0; i2 < FF; i2++)
                v = fmaf(sh_o10[w][i2], sh_lw[i2 * FF + lane], v);
            d_o[n * FF + lane] = v;
            atomicAdd(&sh_bna[lane], v);
            atomicAdd(&sh_bna[FF + lane], v * v);
        }
    }
    __syncthreads();
    if (tid < 2 * FF) atomicAdd(&d_bn2[l * 2 * FF + tid], sh_bna[tid]);
}

// final-layer BN + relu + two-stage global_add_pool; restores d_deg to zero
__global__ void __launch_bounds__(256) k_bnpool(
    const float* __restrict__ gamma, const float* __restrict__ beta,
    const int* __restrict__ batch, int l) {
    __shared__ float sh_pool[GG * FF];
    __shared__ float sh_a[FF], sh_b[FF];
    const int tid = threadIdx.x;
    for (int i = tid; i < GG * FF; i += 256) sh_pool[i] = 0.f;
    if (tid < FF) {
        float mu  = d_bn2[l * 2 * FF + tid] / (float)NN;
        float var = d_bn2[l * 2 * FF + FF + tid] / (float)NN - mu * mu;
        float a = rsqrtf(var + 1e-5f) * __ldg(&gamma[l * FF + tid]);
        sh_a[tid] = a;
        sh_b[tid] = __ldg(&beta[l * FF + tid]) - mu * a;
    }
    __syncthreads();
    int n = blockIdx.x * 256 + tid;
    if (n < NN) {
        int b = batch[n];
        if (b < 0) b = 0;
        if (b >= GG) b = GG - 1;
#pragma unroll
        for (int f = 0; f < FF; f++) {
            float v = fmaxf(fmaf(d_o[n * FF + f], sh_a[f], sh_b[f]), 0.f);
            atomicAdd(&sh_pool[b * FF + f], v);
        }
        d_deg[n] = 0;          // postcondition restore for next run
    }
    __syncthreads();
    for (int i = tid; i < GG * FF; i += 256) {
        float v = sh_pool[i];
        if (v != 0.f) atomicAdd(&d_pool[i], v);
    }
}

// readout; restores d_pool, d_bn2, d_ecnt, d_logsum
__global__ void k_final(const float* __restrict__ w1, const float* __restrict__ b1,
                        const float* __restrict__ w2, const float* __restrict__ b2,
                        float* __restrict__ out) {
    int g = threadIdx.x;
    if (g < 2 * 2 * FF) d_bn2[g] = 0.f;
    if (g == 0) { d_ecnt = 0; d_logsum = 0.f; }
    if (g >= GG) return;
    float pv[FF];
#pragma unroll
    for (int k = 0; k < FF; k++) { pv[k] = d_pool[g * FF + k]; d_pool[g * FF + k] = 0.f; }
    float o = b2[0];
#pragma unroll
    for (int j = 0; j < 5; j++) {
        float hj = b1[j];
#pragma unroll
        for (int k = 0; k < FF; k++) hj += pv[k] * w1[k * 5 + j];
        o += fmaxf(hj, 0.f) * w2[j];
    }
    out[g] = o;
}

// ---------------- launch -----------------------------------------------------
extern "C" void kernel_launch(void* const* d_in, const int* in_sizes, int n_in,
                              void* d_out, int out_size) {
    const float* x        = (const float*)d_in[0];
    const float* edge_emb = (const float*)d_in[1];
    const float* mlp1_w1  = (const float*)d_in[2];
    const float* mlp1_b1  = (const float*)d_in[3];
    const float* mlp1_w2  = (const float*)d_in[4];
    const float* mlp1_b2  = (const float*)d_in[5];
    const float* enc_w    = (const float*)d_in[6];
    const float* enc_b    = (const float*)d_in[7];
    const float* pre_w    = (const float*)d_in[8];
    const float* pre_b    = (const float*)d_in[9];
    const float* post_w   = (const float*)d_in[10];
    const float* post_b   = (const float*)d_in[11];
    const float* lin_w    = (const float*)d_in[12];
    const float* lin_b    = (const float*)d_in[13];
    const float* bn_gamma = (const float*)d_in[14];
    const float* bn_beta  = (const float*)d_in[15];
    const float* mlp2_w1  = (const float*)d_in[16];
    const float* mlp2_b1  = (const float*)d_in[17];
    const float* mlp2_w2  = (const float*)d_in[18];
    const float* mlp2_b2  = (const float*)d_in[19];
    const int* edge_index = (const int*)d_in[20];
    const int* edge_attr  = (const int*)d_in[21];
    const int* batch      = (const int*)d_in[22];
    float* out = (float*)d_out;

    const int TB = 256;
    k_etab<<<2, 256>>>(edge_emb, enc_w, enc_b, pre_w, pre_b, post_w);
    k_pq<<<(NN + 3) / 4, 256>>>(x, mlp1_w1, mlp1_b1, mlp1_w2, mlp1_b2,
                                bn_gamma, bn_beta, pre_w, edge_index, 0, 0);
    k_prep<<<(NN + TB - 1) / TB, TB>>>();
    k_fill<<<(NE / 2 + TB - 1) / TB, TB>>>(edge_index, edge_attr);
    k_agg<<<(NN + 15) / 16, 512>>>(lin_w, lin_b, post_b, 0);
    k_pq<<<(NN + 3) / 4, 256>>>(x, mlp1_w1, mlp1_b1, mlp1_w2, mlp1_b2,
                                bn_gamma, bn_beta, pre_w, edge_index, 1, 1);
    k_agg<<<(NN + 15) / 16, 512>>>(lin_w, lin_b, post_b, 1);
    k_bnpool<<<(NN + TB - 1) / TB, TB>>>(bn_gamma, bn_beta, batch, 1);
    k_final<<<1, 64>>>(mlp2_w1, mlp2_b1, mlp2_w2, mlp2_b2, out);
}

// round 15
// speedup vs baseline: 1.0202x; 1.0156x over previous
#include <cuda_runtime.h>
#include <math.h>
#include <float.h>

#define NN 50000
#define NE 800000
#define FF 10
#define TT 5
#define TF 50
#define QP 64          // padded row stride for d_p / d_q (256B-aligned rows)
#define GG 64

// ---------------- device scratch (postcondition-restored each run) ----------
static __device__ int      d_deg[NN];          // zero at entry, re-zeroed by k_bnpool
static __device__ int      d_offs[NN];
static __device__ int      d_rank[NE];         // per-edge intra-node rank (from k_pq)
static __device__ int      d_ecnt;             // slot counter, re-zeroed by k_final
static __device__ float    d_logsum;           // re-zeroed by k_final
static __device__ unsigned d_csr[NE];          // (src*256 byte-offset) bits 0..23 | attr<<28
static __device__ float    d_h[NN * FF];
static __device__ __align__(256) float d_p[NN * QP];   // pads never written -> stay 0
static __device__ __align__(256) float d_q[NN * QP];
static __device__ float    d_o[NN * FF];
static __device__ float    d_bn2[2 * 2 * FF];  // [layer][sum|sumsq][FF]; re-zeroed by k_final
static __device__ float    d_pool[GG * FF];    // re-zeroed by k_final
static __device__ float    d_c3g[2 * 256];     // prepacked c3 tables (padded to 64/attr)
static __device__ float    d_pw2g[2 * TT * 288]; // prepacked jj-paired post_w

// ---------------- f32x2 packed helpers (sm_103a) -----------------------------
typedef unsigned long long ull;
__device__ __forceinline__ ull pk2f(float x, float y) {
    ull u; asm("mov.b64 %0,{%1,%2};" : "=l"(u) : "f"(x), "f"(y)); return u;
}
__device__ __forceinline__ void upk2f(ull u, float& x, float& y) {
    asm("mov.b64 {%0,%1},%2;" : "=f"(x), "=f"(y) : "l"(u));
}
__device__ __forceinline__ ull add2f(ull a, ull b) {
    ull r; asm("add.rn.f32x2 %0,%1,%2;" : "=l"(r) : "l"(a), "l"(b)); return r;
}
__device__ __forceinline__ ull fma2f(ull a, ull b, ull c) {
    ull r; asm("fma.rn.f32x2 %0,%1,%2,%3;" : "=l"(r) : "l"(a), "l"(b), "l"(c)); return r;
}
__device__ __forceinline__ ull shfl_xor64(ull v, int m) {
    unsigned lo = (unsigned)v, hi = (unsigned)(v >> 32);
    lo = __shfl_xor_sync(0xffffffffu, lo, m);
    hi = __shfl_xor_sync(0xffffffffu, hi, m);
    return ((ull)hi << 32) | lo;
}

// ---------------- fused h-producer + p/q projection (+ deg count + etab) ----
__global__ void __launch_bounds__(256) k_pq(
    const float* __restrict__ x,
    const float* __restrict__ m1w1, const float* __restrict__ m1b1,
    const float* __restrict__ m1w2, const float* __restrict__ m1b2,
    const float* __restrict__ gamma, const float* __restrict__ beta,
    const float* __restrict__ prew,
    const int* __restrict__ ei,
    const float* __restrict__ eemb, const float* __restrict__ encw,
    const float* __restrict__ encb, const float* __restrict__ preb,
    const float* __restrict__ postw,
    int l, int mode)
{
    __shared__ float sh_x[4][FF];
    __shared__ float sh_hid[4][5];
    __shared__ float sh_h[4][FF];
    __shared__ float e4[4 * FF];
    const int tid = threadIdx.x;
    if (mode == 0) {
        // degree count + rank capture (12500*256 = 3.2M >= NE)
        int gid = blockIdx.x * 256 + tid;
        if (gid < NE) {
            int dst = ei[NE + gid];
            if (dst >= 0 && dst < NN)
                d_rank[gid] = atomicAdd(&d_deg[dst], 1);
        }
        // blocks 0/1: prepack layer tables (l = blockIdx.x)
        if (blockIdx.x < 2) {
            const int le = blockIdx.x;
            if (tid < 4 * FF) {
                int a = tid / FF, k = tid % FF;
                float v = __ldg(&encb[le * FF + k]);
#pragma unroll
                for (int j = 0; j < FF; j++)
                    v = fmaf(__ldg(&eemb[a * FF + j]),
                             __ldg(&encw[(le * FF + j) * FF + k]), v);
                e4[tid] = v;
            }
            __syncthreads();
            {
                int a = tid >> 6, f = tid & 63;
                float v = 0.f;
                if (f < TF) {
                    int t = f / FF, ff = f % FF;
                    v = __ldg(&preb[(le * TT + t) * FF + ff]);
#pragma unroll
                    for (int k = 0; k < FF; k++)
                        v = fmaf(e4[a * FF + k],
                                 __ldg(&prew[((le * TT + t) * 3 * FF + 2 * FF + k) * FF + ff]), v);
                }
                d_c3g[le * 256 + tid] = v;
            }
            for (int idx = tid; idx < TT * 288; idx += 256) {
                int t = idx / 288, rr = idx % 288;
                d_pw2g[le * TT * 288 + idx] = (rr < 260) ? postw[(le * TT + t) * 260 + rr] : 0.f;
            }
        }
    }
    const int g = tid >> 6;
    const int tf = tid & 63;
    const int n = blockIdx.x * 4 + g;
    const bool valid = (n < NN);
    if (mode == 0) {
        if (valid && tf < FF) sh_x[g][tf] = x[n * FF + tf];
        __syncthreads();
        if (valid && tf < 5) {
            float hj = __ldg(&m1b1[tf]);
#pragma unroll
            for (int k = 0; k < FF; k++)
                hj = fmaf(sh_x[g][k], __ldg(&m1w1[k * 5 + tf]), hj);
            sh_hid[g][tf] = fmaxf(hj, 0.f);
        }
        __syncthreads();
        if (valid && tf < FF) {
            float v = __ldg(&m1b2[tf]);
#pragma unroll
            for (int j = 0; j < 5; j++)
                v = fmaf(sh_hid[g][j], __ldg(&m1w2[j * FF + tf]), v);
            sh_h[g][tf] = v;
            d_h[n * FF + tf] = v;
        }
    } else {
        if (valid && tf < FF) {
            float mu  = d_bn2[tf] / (float)NN;
            float var = d_bn2[FF + tf] / (float)NN - mu * mu;
            float v = (d_o[n * FF + tf] - mu) * rsqrtf(var + 1e-5f)
                * __ldg(&gamma[(l - 1) * FF + tf]) + __ldg(&beta[(l - 1) * FF + tf]);
            v = fmaxf(v, 0.f);
            sh_h[g][tf] = v;
            d_h[n * FF + tf] = v;
        }
    }
    __syncthreads();
    if (!valid || tf >= TF) return;
    const int t = tf / FF, f = tf % FF;
    const float* W = prew + (size_t)(l * TT + t) * 3 * FF * FF;
    float ap = 0.f, aq = 0.f;
#pragma unroll
    for (int k = 0; k < FF; k++) {
        float hk = sh_h[g][k];
        ap = fmaf(hk, __ldg(&W[k * FF + f]), ap);
        aq = fmaf(hk, __ldg(&W[(FF + k) * FF + f]), aq);
    }
    d_p[n * QP + tf] = ap;
    d_q[n * QP + tf] = aq;
}

// parallel slot-grab CSR offsets (order-free) + log-degree sum
__global__ void k_prep() {
    int n = blockIdx.x * blockDim.x + threadIdx.x;
    int lane = threadIdx.x & 31;
    int dg = (n < NN) ? d_deg[n] : 0;
    int inc = dg;
#pragma unroll
    for (int o = 1; o < 32; o <<= 1) {
        int u = __shfl_up_sync(0xffffffffu, inc, o);
        if (lane >= o) inc += u;
    }
    int total = __shfl_sync(0xffffffffu, inc, 31);
    int base = 0;
    if (lane == 31 && total > 0) base = atomicAdd(&d_ecnt, total);
    base = __shfl_sync(0xffffffffu, base, 31);
    if (n < NN) d_offs[n] = base + inc - dg;
    float ls = (n < NN) ? logf((float)dg + 1.f) : 0.f;
#pragma unroll
    for (int o = 16; o; o >>= 1) ls += __shfl_xor_sync(0xffffffffu, ls, o);
    if (lane == 0) atomicAdd(&d_logsum, ls);
}

// atomic-free CSR scatter: slot = offs[dst] + precomputed rank
__global__ void k_fill(const int* __restrict__ ei, const int* __restrict__ eattr) {
    int i2 = blockIdx.x * blockDim.x + threadIdx.x;   // edge pair index
    if (i2 * 2 >= NE) return;
    int2 srcs = *(const int2*)(ei + 2 * i2);
    int2 dsts = *(const int2*)(ei + NE + 2 * i2);
    int2 atts = *(const int2*)(eattr + 2 * i2);
    int2 rnks = *(const int2*)(d_rank + 2 * i2);
    {
        int src = srcs.x, dst = dsts.x, attr = atts.x & 3;
        if (dst >= 0 && dst < NN) {
            if (src < 0 || src >= NN) src = 0;
            int slot = d_offs[dst] + rnks.x;
            if (slot >= 0 && slot < NE)
                d_csr[slot] = ((unsigned)src << 8) | ((unsigned)attr << 28);
        }
    }
    {
        int src = srcs.y, dst = dsts.y, attr = atts.y & 3;
        if (dst >= 0 && dst < NN) {
            if (src < 0 || src >= NN) src = 0;
            int slot = d_offs[dst] + rnks.y;
            if (slot >= 0 && slot < NE)
                d_csr[slot] = ((unsigned)src << 8) | ((unsigned)attr << 28);
        }
    }
}

// warp-per-node (16 nodes / 512-thread block): float2 gather + packed-f32x2
// stats of m=p+q+c3, jj-packed post matvec + lin + BN sums. Tables preloaded.
__global__ void __launch_bounds__(512, 4) k_agg(
    const float* __restrict__ linw, const float* __restrict__ linb,
    const float* __restrict__ postb, int l)
{
    __shared__ __align__(8) float sh_c3[4 * 64];     // padded to 64, pads = 0
    __shared__ __align__(8) float sh_pw2[TT * 288];  // [t][row*2+jj], rows>129 zero pad
    __shared__ float sh_pb[10];
    __shared__ float sh_lw[FF * FF];
    __shared__ float sh_lb[FF];
    __shared__ float sh_xt[16][FF];
    __shared__ __align__(8) float sh_st[16][4][TF];  // [warp][stat][tf]
    __shared__ float sh_o10[16][10];
    __shared__ float sh_bna[2 * FF];
    __shared__ float sh_avg;
    const int tid = threadIdx.x;
    if (tid < 256) sh_c3[tid] = d_c3g[l * 256 + tid];
    for (int idx = tid; idx < TT * 288; idx += 512)
        sh_pw2[idx] = d_pw2g[l * TT * 288 + idx];
    if (tid < 10) sh_pb[tid] = postb[l * 10 + tid];
    if (tid < FF * FF) sh_lw[tid] = linw[l * FF * FF + tid];
    if (tid < FF) sh_lb[tid] = linb[l * FF + tid];
    if (tid < 2 * FF) sh_bna[tid] = 0.f;
    if (tid == 0) sh_avg = d_logsum * (1.f / (float)NN);
    __syncthreads();

    const int w = tid >> 5, lane = tid & 31;
    const int n = blockIdx.x * 16 + w;
    if (n < NN) {
        const int stt = d_offs[n];
        const int dg  = d_deg[n];
        const int enn = stt + dg;
        const float dclamp = fmaxf((float)dg, 1.f);
        const float invd = 1.f / dclamp;
        const float ld = logf(dclamp + 1.f);
        const float avg = sh_avg;
        const float amp = ld / avg, att = avg / ld;
        if (lane < FF) sh_xt[w][lane] = d_h[n * FF + lane];
        const int fl = 2 * lane;                       // 0..62 (>=50 -> padding)
        const float2 pv = *(const float2*)(d_p + n * QP + fl);
        const ull p01 = pk2f(pv.x, pv.y);
        const char* qb  = (const char*)d_q + (size_t)fl * 4;   // lane base, byte addressed
        const char* c3b = (const char*)sh_c3 + (size_t)fl * 4;
        ull s01 = 0ull, ss01 = 0ull;                   // stats of m = p + q + c3
        float mn0 = FLT_MAX, mx0 = -FLT_MAX, mn1 = FLT_MAX, mx1 = -FLT_MAX;
#define EDGE(pkv) {                                                              \
        const float2 qv = *(const float2*)(qb + ((pkv) & 0x0FFFFFFFu));          \
        const float2 cv = *(const float2*)(c3b + (((pkv) >> 28) << 8));          \
        ull m01 = add2f(add2f(p01, pk2f(qv.x, qv.y)), pk2f(cv.x, cv.y));         \
        s01 = add2f(s01, m01); ss01 = fma2f(m01, m01, ss01);                     \
        float m0, m1; upk2f(m01, m0, m1);                                        \
        mn0 = fminf(mn0, m0); mx0 = fmaxf(mx0, m0);                              \
        mn1 = fminf(mn1, m1); mx1 = fmaxf(mx1, m1); }
        int i = stt;
        for (; i + 4 <= enn; i += 4) {
            unsigned pk0 = d_csr[i],     pk1 = d_csr[i + 1];
            unsigned pk2 = d_csr[i + 2], pk3 = d_csr[i + 3];
            EDGE(pk0); EDGE(pk1); EDGE(pk2); EDGE(pk3);
        }
        for (; i < enn; i++) { unsigned pk = d_csr[i]; EDGE(pk); }
#undef EDGE
        if (fl < TF) {
            float s0, s1, ss0, ss1;
            upk2f(s01, s0, s1); upk2f(ss01, ss0, ss1);
            float mean0 = s0 * invd, mean1 = s1 * invd;
            float std0 = sqrtf(fmaxf(ss0 * invd - mean0 * mean0, 0.f) + 1e-5f);
            float std1 = sqrtf(fmaxf(ss1 * invd - mean1 * mean1, 0.f) + 1e-5f);
            bool hin = dg > 0;
            *(ull*)&sh_st[w][0][fl] = pk2f(mean0, mean1);
            *(ull*)&sh_st[w][1][fl] = pk2f(hin ? mn0 : 0.f, hin ? mn1 : 0.f);
            *(ull*)&sh_st[w][2][fl] = pk2f(hin ? mx0 : 0.f, hin ? mx1 : 0.f);
            *(ull*)&sh_st[w][3][fl] = pk2f(std0, std1);
        }
        __syncwarp();
        // jj-packed post matvec: rows r0=lane (0..31), r1=lane+32 (32..49)
        const int r0 = lane, r1 = lane + 32;
        const bool x0v = (r0 < FF);
        const int s0i = (r0 - FF) / FF, f0i = (r0 - FF) % FF;
        const int s1i = (r1 - FF) / FF, f1i = (r1 - FF) % FF;
        const bool v1 = (r1 < TF);
        const ull amppk = pk2f(amp, amp), attpk = pk2f(att, att);
#pragma unroll
        for (int t = 0; t < TT; t++) {
            const float* P = &sh_pw2[t * 288];
            float iv0 = x0v ? sh_xt[w][r0] : sh_st[w][s0i][t * FF + f0i];
            float iv1 = v1 ? sh_st[w][s1i][t * FF + f1i] : 0.f;
            ull w0 = *(const ull*)(P + 2 * r0);
            if (!x0v) {
                ull w0a = *(const ull*)(P + 2 * (r0 + 40));
                ull w0b = *(const ull*)(P + 2 * (r0 + 80));
                w0 = fma2f(amppk, w0a, fma2f(attpk, w0b, w0));
            }
            ull w1  = *(const ull*)(P + 2 * r1);
            ull w1a = *(const ull*)(P + 2 * (r1 + 40));
            ull w1b = *(const ull*)(P + 2 * (r1 + 80));   // max 2*143 < 288 (pad=0)
            w1 = fma2f(amppk, w1a, fma2f(attpk, w1b, w1));
            ull acc = fma2f(pk2f(iv0, iv0), w0, fma2f(pk2f(iv1, iv1), w1, 0ull));
            acc = add2f(acc, shfl_xor64(acc, 16));
            acc = add2f(acc, shfl_xor64(acc, 8));
            acc = add2f(acc, shfl_xor64(acc, 4));
            acc = add2f(acc, shfl_xor64(acc, 2));
            acc = add2f(acc, shfl_xor64(acc, 1));
            if (lane == 0) {
                float a0, a1; upk2f(acc, a0, a1);
                sh_o10[w][t * 2]     = a0 + sh_pb[t * 2];
                sh_o10[w][t * 2 + 1] = a1 + sh_pb[t * 2 + 1];
            }
        }
        __syncwarp();
        if (lane < FF) {
            float v = sh_lb[lane];
#pragma unroll
            for (int i2 = 0; i2 < FF; i2++)
                v = fmaf(sh_o10[w][i2], sh_lw[i2 * FF + lane], v);
            d_o[n * FF + lane] = v;
            atomicAdd(&sh_bna[lane], v);
            atomicAdd(&sh_bna[FF + lane], v * v);
        }
    }
    __syncthreads();
    if (tid < 2 * FF) atomicAdd(&d_bn2[l * 2 * FF + tid], sh_bna[tid]);
}

// final-layer BN + relu + two-stage global_add_pool; restores d_deg to zero
__global__ void __launch_bounds__(256) k_bnpool(
    const float* __restrict__ gamma, const float* __restrict__ beta,
    const int* __restrict__ batch, int l) {
    __shared__ float sh_pool[GG * FF];
    __shared__ float sh_a[FF], sh_b[FF];
    const int tid = threadIdx.x;
    for (int i = tid; i < GG * FF; i += 256) sh_pool[i] = 0.f;
    if (tid < FF) {
        float mu  = d_bn2[l * 2 * FF + tid] / (float)NN;
        float var = d_bn2[l * 2 * FF + FF + tid] / (float)NN - mu * mu;
        float a = rsqrtf(var + 1e-5f) * __ldg(&gamma[l * FF + tid]);
        sh_a[tid] = a;
        sh_b[tid] = __ldg(&beta[l * FF + tid]) - mu * a;
    }
    __syncthreads();
    int n = blockIdx.x * 256 + tid;
    if (n < NN) {
        int b = batch[n];
        if (b < 0) b = 0;
        if (b >= GG) b = GG - 1;
#pragma unroll
        for (int f = 0; f < FF; f++) {
            float v = fmaxf(fmaf(d_o[n * FF + f], sh_a[f], sh_b[f]), 0.f);
            atomicAdd(&sh_pool[b * FF + f], v);
        }
        d_deg[n] = 0;          // postcondition restore for next run
    }
    __syncthreads();
    for (int i = tid; i < GG * FF; i += 256) {
        float v = sh_pool[i];
        if (v != 0.f) atomicAdd(&d_pool[i], v);
    }
}

// readout; restores d_pool, d_bn2, d_ecnt, d_logsum
__global__ void k_final(const float* __restrict__ w1, const float* __restrict__ b1,
                        const float* __restrict__ w2, const float* __restrict__ b2,
                        float* __restrict__ out) {
    int g = threadIdx.x;
    if (g < 2 * 2 * FF) d_bn2[g] = 0.f;
    if (g == 0) { d_ecnt = 0; d_logsum = 0.f; }
    if (g >= GG) return;
    float pv[FF];
#pragma unroll
    for (int k = 0; k < FF; k++) { pv[k] = d_pool[g * FF + k]; d_pool[g * FF + k] = 0.f; }
    float o = b2[0];
#pragma unroll
    for (int j = 0; j < 5; j++) {
        float hj = b1[j];
#pragma unroll
        for (int k = 0; k < FF; k++) hj += pv[k] * w1[k * 5 + j];
        o += fmaxf(hj, 0.f) * w2[j];
    }
    out[g] = o;
}

// ---------------- launch -----------------------------------------------------
extern "C" void kernel_launch(void* const* d_in, const int* in_sizes, int n_in,
                              void* d_out, int out_size) {
    const float* x        = (const float*)d_in[0];
    const float* edge_emb = (const float*)d_in[1];
    const float* mlp1_w1  = (const float*)d_in[2];
    const float* mlp1_b1  = (const float*)d_in[3];
    const float* mlp1_w2  = (const float*)d_in[4];
    const float* mlp1_b2  = (const float*)d_in[5];
    const float* enc_w    = (const float*)d_in[6];
    const float* enc_b    = (const float*)d_in[7];
    const float* pre_w    = (const float*)d_in[8];
    const float* pre_b    = (const float*)d_in[9];
    const float* post_w   = (const float*)d_in[10];
    const float* post_b   = (const float*)d_in[11];
    const float* lin_w    = (const float*)d_in[12];
    const float* lin_b    = (const float*)d_in[13];
    const float* bn_gamma = (const float*)d_in[14];
    const float* bn_beta  = (const float*)d_in[15];
    const float* mlp2_w1  = (const float*)d_in[16];
    const float* mlp2_b1  = (const float*)d_in[17];
    const float* mlp2_w2  = (const float*)d_in[18];
    const float* mlp2_b2  = (const float*)d_in[19];
    const int* edge_index = (const int*)d_in[20];
    const int* edge_attr  = (const int*)d_in[21];
    const int* batch      = (const int*)d_in[22];
    float* out = (float*)d_out;

    const int TB = 256;
    k_pq<<<(NN + 3) / 4, 256>>>(x, mlp1_w1, mlp1_b1, mlp1_w2, mlp1_b2,
                                bn_gamma, bn_beta, pre_w, edge_index,
                                edge_emb, enc_w, enc_b, pre_b, post_w, 0, 0);
    k_prep<<<(NN + TB - 1) / TB, TB>>>();
    k_fill<<<(NE / 2 + TB - 1) / TB, TB>>>(edge_index, edge_attr);
    k_agg<<<(NN + 15) / 16, 512>>>(lin_w, lin_b, post_b, 0);
    k_pq<<<(NN + 3) / 4, 256>>>(x, mlp1_w1, mlp1_b1, mlp1_w2, mlp1_b2,
                                bn_gamma, bn_beta, pre_w, edge_index,
                                edge_emb, enc_w, enc_b, pre_b, post_w, 1, 1);
    k_agg<<<(NN + 15) / 16, 512>>>(lin_w, lin_b, post_b, 1);
    k_bnpool<<<(NN + TB - 1) / TB, TB>>>(bn_gamma, bn_beta, batch, 1);
    k_final<<<1, 64>>>(mlp2_w1, mlp2_b1, mlp2_w2, mlp2_b2, out);
}